// round 10
// baseline (speedup 1.0000x reference)
#include <cuda_runtime.h>

constexpr int NB = 256;

constexpr int cpopc(int x){int c=0;while(x){c+=x&1;x>>=1;}return c;}

struct Alg {
    int qt[64];
    short kk[64][64];     // k(i,j)
    short sg[64][64];     // sign bit (1 = negative)
    int   cls[4][20];
    int   ncl[4];
    int   perm[4][16];    // row assignment per jq-group (class-grouped)
};
constexpr Alg build_alg(){
    Alg a{};
    int mask[64]={}, pos[64]={};
    int idx=0;
    for(int g=0;g<=6;++g) for(int m=0;m<64;++m) if(cpopc(m)==g){mask[idx]=m;idx++;}
    for(int i=0;i<64;++i) pos[mask[i]]=i;
    for(int i=0;i<64;++i){
        a.qt[i]=cpopc(mask[i])&3;
        a.cls[a.qt[i]][a.ncl[a.qt[i]]]=i;
        a.ncl[a.qt[i]]++;
    }
    for(int i=0;i<64;++i) for(int j=0;j<64;++j){
        const int mk=mask[i]^mask[j];
        const int k=pos[mk];
        int s=0,t=mask[i]>>1;
        while(t){s+=cpopc(t&mk);t>>=1;}
        a.kk[i][j]=(short)k;
        a.sg[i][j]=(short)(s&1);
    }
    // class-grouped permutation: ncl = {16,12,16,20}
    for(int q=0;q<16;++q) a.perm[0][q]=a.cls[0][q];           // 16 x c0
    for(int q=0;q<12;++q) a.perm[1][q]=a.cls[1][q];           // 12 x c1
    for(int q=0;q<4; ++q) a.perm[1][12+q]=a.cls[3][q];        //  4 x c3
    for(int q=0;q<16;++q) a.perm[2][q]=a.cls[2][q];           // 16 x c2
    for(int q=0;q<16;++q) a.perm[3][q]=a.cls[3][4+q];         // 16 x c3
    return a;
}
__device__ constexpr Alg ALG = build_alg();

// ---- packed f32x2 helpers (lin phase) --------------------------------------
typedef unsigned long long ull;

__device__ __forceinline__ ull fma2(ull a, ull b, ull c){
    ull r; asm("fma.rn.f32x2 %0, %1, %2, %3;" : "=l"(r) : "l"(a), "l"(b), "l"(c)); return r;
}
__device__ __forceinline__ void upk2(ull v, float& lo, float& hi){
    unsigned x, y;
    asm("mov.b64 {%0, %1}, %2;" : "=r"(x), "=r"(y) : "l"(v));
    lo = __uint_as_float(x); hi = __uint_as_float(y);
}

// gp_lin_w pre-paired: ull holds (lw[2mp][f], lw[2mp+1][f]) for [l][c][mp][f]
__device__ ull   g_lwT2[4*4*32*64];
__device__ float g_lin1T[1024];      // [m][f]
__device__ float g_loss_scratch[NB];

// Init: one float4 (c=0..3) per (l,f,m); scatter into paired layout.
__global__ void ch_init(const float* __restrict__ gp_lin_w,
                        const float* __restrict__ lin_w)
{
    const int t = threadIdx.x;
    if (blockIdx.x < 64) {
        const int s = blockIdx.x*256 + t;          // (l,f,m), m fastest
        const int m = s & 63, f = (s>>6) & 63, l = s>>12;
        const float4 v = reinterpret_cast<const float4*>(gp_lin_w)[s];
        float* base = reinterpret_cast<float*>(g_lwT2);
        const int mp = m >> 1, half = m & 1;
        base[((((l*4+0)*32 + mp)*64 + f)<<1) + half] = v.x;
        base[((((l*4+1)*32 + mp)*64 + f)<<1) + half] = v.y;
        base[((((l*4+2)*32 + mp)*64 + f)<<1) + half] = v.z;
        base[((((l*4+3)*32 + mp)*64 + f)<<1) + half] = v.w;
    } else {
        #pragma unroll
        for (int r=0;r<4;++r){
            const int e=r*256+t, m=e>>6, f=e&63;
            g_lin1T[e] = lin_w[(f*16+m)*4 + 1];
        }
    }
}

struct SM {
    float A[4096];      // x [i*64+f]
    float Bv[4224];     // xr [i*64+f]; reused for mlp_w1 [f*65+n]
    float W[4160];      // gp_w [f*65+widx]
    float F[256];       // epilogue norm partials [part*64+f]
    float y[64], h[64], pts[96];
};

template<int JQ>
__device__ __forceinline__ void sec_lin(const float* __restrict__ Ash,
                                        float* __restrict__ Bvf,
                                        int l, int f)
{
    ull LW2[32];
    #pragma unroll
    for (int q=0;q<16;++q) {
        constexpr auto P = ALG.perm[JQ];
        const int i = P[q];
        if (q==0 || ALG.qt[P[q]]!=ALG.qt[P[q-1]]) {
            const ull* p = g_lwT2 + ((l*4 + ALG.qt[i])*32)*64 + f;
            #pragma unroll
            for (int mp=0;mp<32;++mp) LW2[mp] = p[mp*64];
        }
        const ulonglong2* Ar = reinterpret_cast<const ulonglong2*>(Ash + i*64);
        ull acca = 0ull, accb = 0ull;
        #pragma unroll
        for (int u=0;u<16;++u){
            const ulonglong2 av = Ar[u];
            acca = fma2(LW2[2*u+0], av.x, acca);
            accb = fma2(LW2[2*u+1], av.y, accb);
        }
        float a0,a1,b0,b1;
        upk2(acca, a0, a1);
        upk2(accb, b0, b1);
        Bvf[i*64] = (a0+b0) + (a1+b1);
    }
}

// GP with fused normalize-factor computation (B column already in regs).
template<int JQ>
__device__ __forceinline__ void sec_gp(const float* __restrict__ Af,
                                       const float* __restrict__ Bvf,
                                       const float* __restrict__ Wf,
                                       const float* __restrict__ gp_a,
                                       int l, int f,
                                       float (&acc)[16])
{
    constexpr int CJ0 = (JQ==0) ? 0 : (JQ==1 ? 1 : (JQ==2 ? 2 : 3));
    constexpr int NCJ = (JQ==1) ? 2 : 1;   // group 1 also carries class-3 rows

    float B[64];
    #pragma unroll
    for (int k=0;k<64;++k) B[k] = Bvf[k*64];

    // per-class sums from registers (redundant across groups, removes a barrier)
    float sum[4] = {0.f,0.f,0.f,0.f};
    #pragma unroll
    for (int k=0;k<64;++k) sum[ALG.qt[k]] = fmaf(B[k], B[k], sum[ALG.qt[k]]);

    float fc[4];
    #pragma unroll
    for (int c=0;c<4;++c){
        const float nrm = sqrtf(fmaxf(sum[c], 1e-12f));
        const float av  = gp_a[(l*64+f)*4 + c];
        const float sig = 1.f/(1.f+expf(-av));
        fc[c] = 1.f/(fmaf(sig, nrm-1.f, 1.f) + 1e-6f);
    }
    #pragma unroll
    for (int k=0;k<64;++k) B[k] *= fc[ALG.qt[k]];

    float Wreg[NCJ*16];
    #pragma unroll
    for (int ci=0;ci<4;++ci)
        #pragma unroll
        for (int ck=0;ck<4;++ck) {
            Wreg[ci*4+ck] = Wf[(ci*4+CJ0)*4+ck];
            if (NCJ==2) Wreg[16+ci*4+ck] = Wf[(ci*4+3)*4+ck];
        }

    #pragma unroll
    for (int q=0;q<16;++q) acc[q]=0.f;

    #pragma unroll
    for (int i=0;i<64;++i) {
        const float xi = Af[i*64];
        const int qti = ALG.qt[i];
        float XW[NCJ*4];
        #pragma unroll
        for (int ck=0;ck<4;++ck) {
            XW[ck] = xi * Wreg[qti*4+ck];
            if (NCJ==2) XW[4+ck] = xi * Wreg[16+qti*4+ck];
        }
        #pragma unroll
        for (int q=0;q<16;++q) {
            const int j  = ALG.perm[JQ][q];
            const int k  = ALG.kk[i][j];
            const int ck = ALG.qt[k];
            const int slot = (JQ==1 && q>=12) ? 1 : 0;
            const float xw = XW[slot*4+ck];
            if (ALG.sg[i][j]) acc[q] = fmaf(xw, -B[k], acc[q]);
            else              acc[q] = fmaf(xw,  B[k], acc[q]);
        }
    }
}

template<int JQ>
__device__ __forceinline__ void sec_store(float* __restrict__ Ash, int f,
                                          const float (&acc)[16])
{
    #pragma unroll
    for (int q=0;q<16;++q)
        Ash[ALG.perm[JQ][q]*64 + f] = acc[q];
}

__global__ void __launch_bounds__(256, 2)
ch_main(const float* __restrict__ points,
        const float* __restrict__ products,
        const float* __restrict__ lin_b,
        const float* __restrict__ gp_a,
        const float* __restrict__ gp_w,
        const float* __restrict__ mlp_w1,
        const float* __restrict__ mlp_b1,
        const float* __restrict__ mlp_w2,
        const float* __restrict__ mlp_b2,
        float* __restrict__ lossp)
{
    extern __shared__ unsigned char smraw[];
    SM* s = reinterpret_cast<SM*>(smraw);

    const int t  = threadIdx.x;
    const int b  = blockIdx.x;
    const int f  = t & 63;
    const int jq = t >> 6;

    if (t < 96) s->pts[t] = points[b*96 + t];
    for (int e = 448 + t; e < 4096; e += 256) s->A[e] = 0.f;
    if (t < 64) s->A[t] = lin_b[t];
    __syncthreads();

    for (int d = jq; d < 6; d += 4) {
        float acc = 0.f;
        #pragma unroll
        for (int m=0;m<16;++m)
            acc = fmaf(s->pts[m*6+d], g_lin1T[m*64+f], acc);
        s->A[(1+d)*64 + f] = acc;
    }
    __syncthreads();

    float acc[16];
    for (int l = 0; l < 4; ++l) {
        {   // stage gp_w: W[f*65+w] via float4 loads
            const float4* gw4 = reinterpret_cast<const float4*>(gp_w + l*4096);
            #pragma unroll
            for (int r=0;r<4;++r) {
                const int e4 = r*256+t;
                const float4 v = gw4[e4];
                const int e = e4*4, ff = e>>6, w = e&63;
                s->W[ff*65+w+0] = v.x;
                s->W[ff*65+w+1] = v.y;
                s->W[ff*65+w+2] = v.z;
                s->W[ff*65+w+3] = v.w;
            }
        }
        switch (jq) {
            case 0:  sec_lin<0>(s->A, s->Bv+f, l, f); break;
            case 1:  sec_lin<1>(s->A, s->Bv+f, l, f); break;
            case 2:  sec_lin<2>(s->A, s->Bv+f, l, f); break;
            default: sec_lin<3>(s->A, s->Bv+f, l, f); break;
        }
        __syncthreads();
        switch (jq) {
            case 0:  sec_gp<0>(s->A+f, s->Bv+f, s->W+f*65, gp_a, l, f, acc); break;
            case 1:  sec_gp<1>(s->A+f, s->Bv+f, s->W+f*65, gp_a, l, f, acc); break;
            case 2:  sec_gp<2>(s->A+f, s->Bv+f, s->W+f*65, gp_a, l, f, acc); break;
            default: sec_gp<3>(s->A+f, s->Bv+f, s->W+f*65, gp_a, l, f, acc); break;
        }
        __syncthreads();
        switch (jq) {
            case 0:  sec_store<0>(s->A, f, acc); break;
            case 1:  sec_store<1>(s->A, f, acc); break;
            case 2:  sec_store<2>(s->A, f, acc); break;
            default: sec_store<3>(s->A, f, acc); break;
        }
        __syncthreads();
    }

    // epilogue: norms, MLP, loss
    {
        float sum = 0.f;
        #pragma unroll
        for (int r=0;r<16;++r) {
            const float v = s->A[(jq*16+r)*64+f];
            sum = fmaf(v, v, sum);
        }
        s->F[jq*64+f] = sum;
    }
    {   // stage mlp_w1 -> Bv[f*65+n] via float4
        const float4* mw4 = reinterpret_cast<const float4*>(mlp_w1);
        #pragma unroll
        for (int r=0;r<4;++r) {
            const int e4 = r*256+t;
            const float4 v = mw4[e4];
            const int e = e4*4, n = e>>6, ff = e&63;
            s->Bv[(ff+0)*65+n] = v.x;
            s->Bv[(ff+1)*65+n] = v.y;
            s->Bv[(ff+2)*65+n] = v.z;
            s->Bv[(ff+3)*65+n] = v.w;
        }
    }
    __syncthreads();
    if (t < 64) s->y[t] = sqrtf(s->F[t] + s->F[64+t] + s->F[128+t] + s->F[192+t]);
    __syncthreads();
    if (t < 64) {
        float a = mlp_b1[t];
        #pragma unroll
        for (int ff=0;ff<64;++ff)
            a = fmaf(s->y[ff], s->Bv[ff*65+t], a);
        const float sig = 1.f/(1.f+expf(-a));
        s->h[t] = a * sig * mlp_w2[t];
    }
    __syncthreads();
    if (t == 0) {
        float p = mlp_b2[0];
        for (int n=0;n<64;++n) p += s->h[n];
        const float d = p - products[b];
        lossp[b] = d*d;
    }
}

__global__ void ch_reduce(const float* __restrict__ lossp, float* __restrict__ out)
{
    __shared__ float sred[NB];
    const int t = threadIdx.x;
    sred[t] = lossp[t];
    __syncthreads();
    for (int sft = NB/2; sft > 0; sft >>= 1) {
        if (t < sft) sred[t] += sred[t+sft];
        __syncthreads();
    }
    if (t == 0) out[0] = sred[0] * (1.0f/(float)NB);
}

extern "C" void kernel_launch(void* const* d_in, const int* in_sizes, int n_in,
                              void* d_out, int out_size)
{
    const float* points   = (const float*)d_in[0];
    const float* products = (const float*)d_in[1];
    const float* lin_w    = (const float*)d_in[2];
    const float* lin_b    = (const float*)d_in[3];
    const float* gp_lin_w = (const float*)d_in[4];
    const float* gp_a     = (const float*)d_in[5];
    const float* gp_w     = (const float*)d_in[6];
    const float* mlp_w1   = (const float*)d_in[7];
    const float* mlp_b1   = (const float*)d_in[8];
    const float* mlp_w2   = (const float*)d_in[9];
    const float* mlp_b2   = (const float*)d_in[10];
    float* out = (float*)d_out;

    static bool attr_set = false;
    if (!attr_set) {
        cudaFuncSetAttribute(ch_main, cudaFuncAttributeMaxDynamicSharedMemorySize,
                             (int)sizeof(SM));
        attr_set = true;
    }

    ch_init<<<65, 256>>>(gp_lin_w, lin_w);

    float* lossp;
    bool write_mean = true;
    if (out_size >= NB + 1) {
        lossp = out + 1;
    } else if (out_size == NB) {
        lossp = out; write_mean = false;
    } else {
        void* p = nullptr;
        cudaGetSymbolAddress(&p, g_loss_scratch);
        lossp = (float*)p;
    }

    ch_main<<<NB, 256, sizeof(SM)>>>(points, products, lin_b, gp_a, gp_w,
                                     mlp_w1, mlp_b1, mlp_w2, mlp_b2, lossp);
    if (write_mean)
        ch_reduce<<<1, NB>>>(lossp, out);
}

// round 11
// speedup vs baseline: 1.1793x; 1.1793x over previous
#include <cuda_runtime.h>

constexpr int NB = 256;

constexpr int cpopc(int x){int c=0;while(x){c+=x&1;x>>=1;}return c;}

struct Alg {
    int qt[64];
    short kk[64][64];     // k(i,j)
    short sg[64][64];     // sign bit (1 = negative)
    int   cls[4][20];
    int   ncl[4];
    int   perm[4][16];    // row assignment per jq-group (class-grouped)
};
constexpr Alg build_alg(){
    Alg a{};
    int mask[64]={}, pos[64]={};
    int idx=0;
    for(int g=0;g<=6;++g) for(int m=0;m<64;++m) if(cpopc(m)==g){mask[idx]=m;idx++;}
    for(int i=0;i<64;++i) pos[mask[i]]=i;
    for(int i=0;i<64;++i){
        a.qt[i]=cpopc(mask[i])&3;
        a.cls[a.qt[i]][a.ncl[a.qt[i]]]=i;
        a.ncl[a.qt[i]]++;
    }
    for(int i=0;i<64;++i) for(int j=0;j<64;++j){
        const int mk=mask[i]^mask[j];
        const int k=pos[mk];
        int s=0,t=mask[i]>>1;
        while(t){s+=cpopc(t&mk);t>>=1;}
        a.kk[i][j]=(short)k;
        a.sg[i][j]=(short)(s&1);
    }
    // class-grouped permutation: ncl = {16,12,16,20}
    for(int q=0;q<16;++q) a.perm[0][q]=a.cls[0][q];           // 16 x c0
    for(int q=0;q<12;++q) a.perm[1][q]=a.cls[1][q];           // 12 x c1
    for(int q=0;q<4; ++q) a.perm[1][12+q]=a.cls[3][q];        //  4 x c3
    for(int q=0;q<16;++q) a.perm[2][q]=a.cls[2][q];           // 16 x c2
    for(int q=0;q<16;++q) a.perm[3][q]=a.cls[3][4+q];         // 16 x c3
    return a;
}
__device__ constexpr Alg ALG = build_alg();

// ---- packed f32x2 helpers (lin phase) --------------------------------------
typedef unsigned long long ull;

__device__ __forceinline__ ull fma2(ull a, ull b, ull c){
    ull r; asm("fma.rn.f32x2 %0, %1, %2, %3;" : "=l"(r) : "l"(a), "l"(b), "l"(c)); return r;
}
__device__ __forceinline__ void upk2(ull v, float& lo, float& hi){
    unsigned x, y;
    asm("mov.b64 {%0, %1}, %2;" : "=r"(x), "=r"(y) : "l"(v));
    lo = __uint_as_float(x); hi = __uint_as_float(y);
}

// gp_lin_w pre-paired: ull holds (lw[2mp][f], lw[2mp+1][f]) for [l][c][mp][f]
__device__ ull   g_lwT2[4*4*32*64];
__device__ float g_lin1T[1024];      // [m][f]
__device__ float g_loss_scratch[NB];

// Init: one float4 (c=0..3) per (l,f,m); scatter into paired layout.
__global__ void ch_init(const float* __restrict__ gp_lin_w,
                        const float* __restrict__ lin_w)
{
    const int t = threadIdx.x;
    if (blockIdx.x < 64) {
        const int s = blockIdx.x*256 + t;          // (l,f,m), m fastest
        const int m = s & 63, f = (s>>6) & 63, l = s>>12;
        const float4 v = reinterpret_cast<const float4*>(gp_lin_w)[s];
        float* base = reinterpret_cast<float*>(g_lwT2);
        const int mp = m >> 1, half = m & 1;
        base[((((l*4+0)*32 + mp)*64 + f)<<1) + half] = v.x;
        base[((((l*4+1)*32 + mp)*64 + f)<<1) + half] = v.y;
        base[((((l*4+2)*32 + mp)*64 + f)<<1) + half] = v.z;
        base[((((l*4+3)*32 + mp)*64 + f)<<1) + half] = v.w;
    } else {
        #pragma unroll
        for (int r=0;r<4;++r){
            const int e=r*256+t, m=e>>6, f=e&63;
            g_lin1T[e] = lin_w[(f*16+m)*4 + 1];
        }
    }
}

struct SM {
    float A[4096];      // x [i*64+f]
    float Bv[4224];     // xr [i*64+f]; reused for mlp_w1 [f*65+n]
    float W[4160];      // gp_w [f*65+widx]
    float F[256];       // normalize factors [c*64+f] / epilogue partials
    float y[64], h[64], pts[96];
};

template<int JQ>
__device__ __forceinline__ void sec_lin(const float* __restrict__ Ash,
                                        float* __restrict__ Bvf,
                                        int l, int f)
{
    ull LW2[32];
    #pragma unroll
    for (int q=0;q<16;++q) {
        constexpr auto P = ALG.perm[JQ];
        const int i = P[q];
        if (q==0 || ALG.qt[P[q]]!=ALG.qt[P[q-1]]) {
            const ull* p = g_lwT2 + ((l*4 + ALG.qt[i])*32)*64 + f;
            #pragma unroll
            for (int mp=0;mp<32;++mp) LW2[mp] = p[mp*64];
        }
        const ulonglong2* Ar = reinterpret_cast<const ulonglong2*>(Ash + i*64);
        ull acca = 0ull, accb = 0ull;
        #pragma unroll
        for (int u=0;u<16;++u){
            const ulonglong2 av = Ar[u];
            acca = fma2(LW2[2*u+0], av.x, acca);
            accb = fma2(LW2[2*u+1], av.y, accb);
        }
        float a0,a1,b0,b1;
        upk2(acca, a0, a1);
        upk2(accb, b0, b1);
        Bvf[i*64] = (a0+b0) + (a1+b1);
    }
}

template<int C>
__device__ __forceinline__ void sec_fact(const float* __restrict__ Bvf,
                                         float* __restrict__ Ff,
                                         const float* __restrict__ gp_a,
                                         int l, int f)
{
    float s = 0.f;
    #pragma unroll
    for (int u=0; u<ALG.ncl[C]; ++u) {
        const float v = Bvf[ALG.cls[C][u]*64];
        s = fmaf(v, v, s);
    }
    const float nrm = sqrtf(fmaxf(s, 1e-12f));
    const float av  = gp_a[(l*64+f)*4 + C];
    const float sig = 1.f/(1.f+expf(-av));
    Ff[C*64] = 1.f/(fmaf(sig, nrm-1.f, 1.f) + 1e-6f);
}

// GP: acc[q] += XW[qt_k] * (+-B[k]), XW[ck] = x_i * w[qt_i][CJ][ck]
template<int JQ>
__device__ __forceinline__ void sec_gp(const float* __restrict__ Af,
                                       const float* __restrict__ Bvf,
                                       const float* __restrict__ Wf,
                                       const float* __restrict__ Ff,
                                       float (&acc)[16])
{
    constexpr int CJ0 = (JQ==0) ? 0 : (JQ==1 ? 1 : (JQ==2 ? 2 : 3));
    constexpr int NCJ = (JQ==1) ? 2 : 1;   // group 1 also carries class-3 rows

    float fc[4];
    #pragma unroll
    for (int c=0;c<4;++c) fc[c] = Ff[c*64];
    float B[64];
    #pragma unroll
    for (int k=0;k<64;++k) B[k] = Bvf[k*64] * fc[ALG.qt[k]];

    float Wreg[NCJ*16];
    #pragma unroll
    for (int ci=0;ci<4;++ci)
        #pragma unroll
        for (int ck=0;ck<4;++ck) {
            Wreg[ci*4+ck] = Wf[(ci*4+CJ0)*4+ck];
            if (NCJ==2) Wreg[16+ci*4+ck] = Wf[(ci*4+3)*4+ck];
        }

    #pragma unroll
    for (int q=0;q<16;++q) acc[q]=0.f;

    #pragma unroll
    for (int i=0;i<64;++i) {
        const float xi = Af[i*64];
        const int qti = ALG.qt[i];
        float XW[NCJ*4];
        #pragma unroll
        for (int ck=0;ck<4;++ck) {
            XW[ck] = xi * Wreg[qti*4+ck];
            if (NCJ==2) XW[4+ck] = xi * Wreg[16+qti*4+ck];
        }
        #pragma unroll
        for (int q=0;q<16;++q) {
            const int j  = ALG.perm[JQ][q];
            const int k  = ALG.kk[i][j];
            const int ck = ALG.qt[k];
            const int slot = (JQ==1 && q>=12) ? 1 : 0;
            const float xw = XW[slot*4+ck];
            if (ALG.sg[i][j]) acc[q] = fmaf(xw, -B[k], acc[q]);
            else              acc[q] = fmaf(xw,  B[k], acc[q]);
        }
    }
}

template<int JQ>
__device__ __forceinline__ void sec_store(float* __restrict__ Ash, int f,
                                          const float (&acc)[16])
{
    #pragma unroll
    for (int q=0;q<16;++q)
        Ash[ALG.perm[JQ][q]*64 + f] = acc[q];
}

__global__ void __launch_bounds__(256, 2)
ch_main(const float* __restrict__ points,
        const float* __restrict__ products,
        const float* __restrict__ lin_b,
        const float* __restrict__ gp_a,
        const float* __restrict__ gp_w,
        const float* __restrict__ mlp_w1,
        const float* __restrict__ mlp_b1,
        const float* __restrict__ mlp_w2,
        const float* __restrict__ mlp_b2,
        float* __restrict__ lossp)
{
    extern __shared__ unsigned char smraw[];
    SM* s = reinterpret_cast<SM*>(smraw);

    const int t  = threadIdx.x;
    const int b  = blockIdx.x;
    const int f  = t & 63;
    const int jq = t >> 6;

    if (t < 96) s->pts[t] = points[b*96 + t];
    for (int e = 448 + t; e < 4096; e += 256) s->A[e] = 0.f;
    if (t < 64) s->A[t] = lin_b[t];
    __syncthreads();

    for (int d = jq; d < 6; d += 4) {
        float acc = 0.f;
        #pragma unroll
        for (int m=0;m<16;++m)
            acc = fmaf(s->pts[m*6+d], g_lin1T[m*64+f], acc);
        s->A[(1+d)*64 + f] = acc;
    }
    __syncthreads();

    float acc[16];
    for (int l = 0; l < 4; ++l) {
        {   // stage gp_w: W[f*65+w] via float4 loads
            const float4* gw4 = reinterpret_cast<const float4*>(gp_w + l*4096);
            #pragma unroll
            for (int r=0;r<4;++r) {
                const int e4 = r*256+t;
                const float4 v = gw4[e4];
                const int e = e4*4, ff = e>>6, w = e&63;
                s->W[ff*65+w+0] = v.x;
                s->W[ff*65+w+1] = v.y;
                s->W[ff*65+w+2] = v.z;
                s->W[ff*65+w+3] = v.w;
            }
        }
        switch (jq) {
            case 0:  sec_lin<0>(s->A, s->Bv+f, l, f); break;
            case 1:  sec_lin<1>(s->A, s->Bv+f, l, f); break;
            case 2:  sec_lin<2>(s->A, s->Bv+f, l, f); break;
            default: sec_lin<3>(s->A, s->Bv+f, l, f); break;
        }
        __syncthreads();
        switch (jq) {
            case 0:  sec_fact<0>(s->Bv+f, s->F+f, gp_a, l, f); break;
            case 1:  sec_fact<1>(s->Bv+f, s->F+f, gp_a, l, f); break;
            case 2:  sec_fact<2>(s->Bv+f, s->F+f, gp_a, l, f); break;
            default: sec_fact<3>(s->Bv+f, s->F+f, gp_a, l, f); break;
        }
        __syncthreads();
        switch (jq) {
            case 0:  sec_gp<0>(s->A+f, s->Bv+f, s->W+f*65, s->F+f, acc); break;
            case 1:  sec_gp<1>(s->A+f, s->Bv+f, s->W+f*65, s->F+f, acc); break;
            case 2:  sec_gp<2>(s->A+f, s->Bv+f, s->W+f*65, s->F+f, acc); break;
            default: sec_gp<3>(s->A+f, s->Bv+f, s->W+f*65, s->F+f, acc); break;
        }
        __syncthreads();
        switch (jq) {
            case 0:  sec_store<0>(s->A, f, acc); break;
            case 1:  sec_store<1>(s->A, f, acc); break;
            case 2:  sec_store<2>(s->A, f, acc); break;
            default: sec_store<3>(s->A, f, acc); break;
        }
        __syncthreads();
    }

    // epilogue: norms, MLP, loss
    {
        float sum = 0.f;
        #pragma unroll
        for (int r=0;r<16;++r) {
            const float v = s->A[(jq*16+r)*64+f];
            sum = fmaf(v, v, sum);
        }
        s->F[jq*64+f] = sum;
    }
    {   // stage mlp_w1 -> Bv[f*65+n] via float4
        const float4* mw4 = reinterpret_cast<const float4*>(mlp_w1);
        #pragma unroll
        for (int r=0;r<4;++r) {
            const int e4 = r*256+t;
            const float4 v = mw4[e4];
            const int e = e4*4, n = e>>6, ff = e&63;
            s->Bv[(ff+0)*65+n] = v.x;
            s->Bv[(ff+1)*65+n] = v.y;
            s->Bv[(ff+2)*65+n] = v.z;
            s->Bv[(ff+3)*65+n] = v.w;
        }
    }
    __syncthreads();
    if (t < 64) s->y[t] = sqrtf(s->F[t] + s->F[64+t] + s->F[128+t] + s->F[192+t]);
    __syncthreads();
    if (t < 64) {
        float a = mlp_b1[t];
        #pragma unroll
        for (int ff=0;ff<64;++ff)
            a = fmaf(s->y[ff], s->Bv[ff*65+t], a);
        const float sig = 1.f/(1.f+expf(-a));
        s->h[t] = a * sig * mlp_w2[t];
    }
    __syncthreads();
    if (t == 0) {
        float p = mlp_b2[0];
        for (int n=0;n<64;++n) p += s->h[n];
        const float d = p - products[b];
        lossp[b] = d*d;
    }
}

__global__ void ch_reduce(const float* __restrict__ lossp, float* __restrict__ out)
{
    __shared__ float sred[NB];
    const int t = threadIdx.x;
    sred[t] = lossp[t];
    __syncthreads();
    for (int sft = NB/2; sft > 0; sft >>= 1) {
        if (t < sft) sred[t] += sred[t+sft];
        __syncthreads();
    }
    if (t == 0) out[0] = sred[0] * (1.0f/(float)NB);
}

extern "C" void kernel_launch(void* const* d_in, const int* in_sizes, int n_in,
                              void* d_out, int out_size)
{
    const float* points   = (const float*)d_in[0];
    const float* products = (const float*)d_in[1];
    const float* lin_w    = (const float*)d_in[2];
    const float* lin_b    = (const float*)d_in[3];
    const float* gp_lin_w = (const float*)d_in[4];
    const float* gp_a     = (const float*)d_in[5];
    const float* gp_w     = (const float*)d_in[6];
    const float* mlp_w1   = (const float*)d_in[7];
    const float* mlp_b1   = (const float*)d_in[8];
    const float* mlp_w2   = (const float*)d_in[9];
    const float* mlp_b2   = (const float*)d_in[10];
    float* out = (float*)d_out;

    static bool attr_set = false;
    if (!attr_set) {
        cudaFuncSetAttribute(ch_main, cudaFuncAttributeMaxDynamicSharedMemorySize,
                             (int)sizeof(SM));
        attr_set = true;
    }

    ch_init<<<65, 256>>>(gp_lin_w, lin_w);

    float* lossp;
    bool write_mean = true;
    if (out_size >= NB + 1) {
        lossp = out + 1;
    } else if (out_size == NB) {
        lossp = out; write_mean = false;
    } else {
        void* p = nullptr;
        cudaGetSymbolAddress(&p, g_loss_scratch);
        lossp = (float*)p;
    }

    ch_main<<<NB, 256, sizeof(SM)>>>(points, products, lin_b, gp_a, gp_w,
                                     mlp_w1, mlp_b1, mlp_w2, mlp_b2, lossp);
    if (write_mean)
        ch_reduce<<<1, NB>>>(lossp, out);
}

// round 13
// speedup vs baseline: 1.1839x; 1.0039x over previous
#include <cuda_runtime.h>

constexpr int NB = 256;

constexpr int cpopc(int x){int c=0;while(x){c+=x&1;x>>=1;}return c;}

struct Alg {
    int qt[64];
    short kk[64][64];     // k(i,j)
    short sg[64][64];     // sign bit (1 = negative)
    int   cls[4][20];
    int   ncl[4];
    int   perm[4][16];    // row assignment per jq-group (class-grouped)
    int   permAll[64];    // concatenated perms: storage order p -> row i
    int   ppos[64];       // row i -> storage position p
};
constexpr Alg build_alg(){
    Alg a{};
    int mask[64]={}, pos[64]={};
    int idx=0;
    for(int g=0;g<=6;++g) for(int m=0;m<64;++m) if(cpopc(m)==g){mask[idx]=m;idx++;}
    for(int i=0;i<64;++i) pos[mask[i]]=i;
    for(int i=0;i<64;++i){
        a.qt[i]=cpopc(mask[i])&3;
        a.cls[a.qt[i]][a.ncl[a.qt[i]]]=i;
        a.ncl[a.qt[i]]++;
    }
    for(int i=0;i<64;++i) for(int j=0;j<64;++j){
        const int mk=mask[i]^mask[j];
        const int k=pos[mk];
        int s=0,t=mask[i]>>1;
        while(t){s+=cpopc(t&mk);t>>=1;}
        a.kk[i][j]=(short)k;
        a.sg[i][j]=(short)(s&1);
    }
    // class-grouped permutation: ncl = {16,12,16,20}
    for(int q=0;q<16;++q) a.perm[0][q]=a.cls[0][q];           // 16 x c0
    for(int q=0;q<12;++q) a.perm[1][q]=a.cls[1][q];           // 12 x c1
    for(int q=0;q<4; ++q) a.perm[1][12+q]=a.cls[3][q];        //  4 x c3
    for(int q=0;q<16;++q) a.perm[2][q]=a.cls[2][q];           // 16 x c2
    for(int q=0;q<16;++q) a.perm[3][q]=a.cls[3][4+q];         // 16 x c3
    for(int g=0;g<4;++g) for(int q=0;q<16;++q){
        a.permAll[g*16+q]=a.perm[g][q];
        a.ppos[a.perm[g][q]]=g*16+q;
    }
    return a;
}
__device__ constexpr Alg ALG = build_alg();

// ---- packed f32x2 helpers (lin phase) --------------------------------------
typedef unsigned long long ull;

__device__ __forceinline__ ull fma2(ull a, ull b, ull c){
    ull r; asm("fma.rn.f32x2 %0, %1, %2, %3;" : "=l"(r) : "l"(a), "l"(b), "l"(c)); return r;
}
__device__ __forceinline__ void upk2(ull v, float& lo, float& hi){
    unsigned x, y;
    asm("mov.b64 {%0, %1}, %2;" : "=r"(x), "=r"(y) : "l"(v));
    lo = __uint_as_float(x); hi = __uint_as_float(y);
}

// gp_lin_w pre-paired: ull holds (lw[2mp][f], lw[2mp+1][f]) for [l][c][mp][f]
__device__ ull      g_lwT2[4*4*32*64];
__device__ float    g_lin1T[1024];      // [m][f]
__device__ float    g_loss_scratch[NB];
__device__ unsigned g_done;

// Init: one float4 (c=0..3) per (l,f,m); scatter into paired layout.
__global__ void ch_init(const float* __restrict__ gp_lin_w,
                        const float* __restrict__ lin_w)
{
    const int t = threadIdx.x;
    if (blockIdx.x < 64) {
        const int s = blockIdx.x*256 + t;          // (l,f,m), m fastest
        const int m = s & 63, f = (s>>6) & 63, l = s>>12;
        const float4 v = reinterpret_cast<const float4*>(gp_lin_w)[s];
        float* base = reinterpret_cast<float*>(g_lwT2);
        const int mp = m >> 1, half = m & 1;
        base[((((l*4+0)*32 + mp)*64 + f)<<1) + half] = v.x;
        base[((((l*4+1)*32 + mp)*64 + f)<<1) + half] = v.y;
        base[((((l*4+2)*32 + mp)*64 + f)<<1) + half] = v.z;
        base[((((l*4+3)*32 + mp)*64 + f)<<1) + half] = v.w;
    } else {
        if (t == 0) g_done = 0u;
        #pragma unroll
        for (int r=0;r<4;++r){
            const int e=r*256+t, m=e>>6, f=e&63;
            g_lin1T[e] = lin_w[(f*16+m)*4 + 1];
        }
    }
}

struct SM {
    float A[4096];      // x row-major [i*64+f] (for lin reads)
    float At[4352];     // x transposed/permuted [f*68+p]
    float Bvt[4352];    // xr transposed/permuted [f*68+p]; reused for mlp_w1 [f*65+n]
    float W[4160];      // gp_w [f*65+widx]
    float F[256];       // normalize factors [c*64+f] / epilogue partials / reduce
    float y[64], h[64], pts[96];
};

template<int JQ>
__device__ __forceinline__ void sec_lin(const float* __restrict__ Ash,
                                        float* __restrict__ Bvt,
                                        int l, int f)
{
    ull LW2[32];
    float out[16];
    #pragma unroll
    for (int q=0;q<16;++q) {
        constexpr auto P = ALG.perm[JQ];
        const int i = P[q];
        if (q==0 || ALG.qt[P[q]]!=ALG.qt[P[q-1]]) {
            const ull* p = g_lwT2 + ((l*4 + ALG.qt[i])*32)*64 + f;
            #pragma unroll
            for (int mp=0;mp<32;++mp) LW2[mp] = p[mp*64];
        }
        const ulonglong2* Ar = reinterpret_cast<const ulonglong2*>(Ash + i*64);
        ull acca = 0ull, accb = 0ull;
        #pragma unroll
        for (int u=0;u<16;++u){
            const ulonglong2 av = Ar[u];
            acca = fma2(LW2[2*u+0], av.x, acca);
            accb = fma2(LW2[2*u+1], av.y, accb);
        }
        float a0,a1,b0,b1;
        upk2(acca, a0, a1);
        upk2(accb, b0, b1);
        out[q] = (a0+b0) + (a1+b1);
    }
    float4* dst = reinterpret_cast<float4*>(Bvt + f*68 + JQ*16);
    #pragma unroll
    for (int r=0;r<4;++r)
        dst[r] = make_float4(out[4*r+0], out[4*r+1], out[4*r+2], out[4*r+3]);
}

template<int C>
__device__ __forceinline__ void sec_fact(const float* __restrict__ Bvtf,
                                         float* __restrict__ Ff,
                                         const float* __restrict__ gp_a,
                                         int l, int f)
{
    float s = 0.f;
    #pragma unroll
    for (int u=0; u<ALG.ncl[C]; ++u) {
        const float v = Bvtf[ALG.ppos[ALG.cls[C][u]]];
        s = fmaf(v, v, s);
    }
    const float nrm = sqrtf(fmaxf(s, 1e-12f));
    const float av  = gp_a[(l*64+f)*4 + C];
    const float sig = 1.f/(1.f+expf(-av));
    Ff[C*64] = 1.f/(fmaf(sig, nrm-1.f, 1.f) + 1e-6f);
}

// GP: acc[q] += XW[qt_k] * (+-B[k]), XW[ck] = x_i * w[qt_i][CJ][ck]
template<int JQ>
__device__ __forceinline__ void sec_gp(const float* __restrict__ Atf,
                                       const float* __restrict__ Bvtf,
                                       const float* __restrict__ Wf,
                                       const float* __restrict__ Ff,
                                       float (&acc)[16])
{
    constexpr int CJ0 = (JQ==0) ? 0 : (JQ==1 ? 1 : (JQ==2 ? 2 : 3));
    constexpr int NCJ = (JQ==1) ? 2 : 1;   // group 1 also carries class-3 rows

    float fc[4];
    #pragma unroll
    for (int c=0;c<4;++c) fc[c] = Ff[c*64];

    float B[64];
    {
        const float4* Bp = reinterpret_cast<const float4*>(Bvtf);
        #pragma unroll
        for (int p4=0;p4<16;++p4){
            const float4 v = Bp[p4];
            #pragma unroll
            for (int h=0;h<4;++h){
                const int k = ALG.permAll[p4*4+h];
                const float bv = (h==0)?v.x:(h==1)?v.y:(h==2)?v.z:v.w;
                B[k] = bv * fc[ALG.qt[k]];
            }
        }
    }

    float Wreg[NCJ*16];
    #pragma unroll
    for (int ci=0;ci<4;++ci)
        #pragma unroll
        for (int ck=0;ck<4;++ck) {
            Wreg[ci*4+ck] = Wf[(ci*4+CJ0)*4+ck];
            if (NCJ==2) Wreg[16+ci*4+ck] = Wf[(ci*4+3)*4+ck];
        }

    #pragma unroll
    for (int q=0;q<16;++q) acc[q]=0.f;

    const float4* Xp = reinterpret_cast<const float4*>(Atf);
    #pragma unroll
    for (int p4=0;p4<16;++p4) {
        const float4 xv = Xp[p4];
        #pragma unroll
        for (int h=0;h<4;++h) {
            const int i = ALG.permAll[p4*4+h];
            const float xi = (h==0)?xv.x:(h==1)?xv.y:(h==2)?xv.z:xv.w;
            const int qti = ALG.qt[i];
            float XW[NCJ*4];
            #pragma unroll
            for (int ck=0;ck<4;++ck) {
                XW[ck] = xi * Wreg[qti*4+ck];
                if (NCJ==2) XW[4+ck] = xi * Wreg[16+qti*4+ck];
            }
            #pragma unroll
            for (int q=0;q<16;++q) {
                const int j  = ALG.perm[JQ][q];
                const int k  = ALG.kk[i][j];
                const int ck = ALG.qt[k];
                const int slot = (JQ==1 && q>=12) ? 1 : 0;
                const float xw = XW[slot*4+ck];
                if (ALG.sg[i][j]) acc[q] = fmaf(xw, -B[k], acc[q]);
                else              acc[q] = fmaf(xw,  B[k], acc[q]);
            }
        }
    }
}

template<int JQ>
__device__ __forceinline__ void sec_store(float* __restrict__ Ash,
                                          float* __restrict__ At,
                                          int f, int l,
                                          const float (&acc)[16])
{
    float4* dstT = reinterpret_cast<float4*>(At + f*68 + JQ*16);
    #pragma unroll
    for (int r=0;r<4;++r)
        dstT[r] = make_float4(acc[4*r+0], acc[4*r+1], acc[4*r+2], acc[4*r+3]);
    if (l < 3) {
        #pragma unroll
        for (int q=0;q<16;++q)
            Ash[ALG.perm[JQ][q]*64 + f] = acc[q];
    }
}

__global__ void __launch_bounds__(256, 2)
ch_main(const float* __restrict__ points,
        const float* __restrict__ products,
        const float* __restrict__ lin_b,
        const float* __restrict__ gp_a,
        const float* __restrict__ gp_w,
        const float* __restrict__ mlp_w1,
        const float* __restrict__ mlp_b1,
        const float* __restrict__ mlp_w2,
        const float* __restrict__ mlp_b2,
        float* __restrict__ lossp,
        float* __restrict__ meanp,
        int do_mean)
{
    extern __shared__ unsigned char smraw[];
    SM* s = reinterpret_cast<SM*>(smraw);

    const int t  = threadIdx.x;
    const int b  = blockIdx.x;
    const int f  = t & 63;
    const int jq = t >> 6;

    if (t < 96) s->pts[t] = points[b*96 + t];
    for (int e = 448 + t; e < 4096; e += 256) s->A[e] = 0.f;
    for (int e = t; e < 4352; e += 256) s->At[e] = 0.f;
    __syncthreads();

    if (t < 64) {
        const float bv = lin_b[t];
        s->A[t] = bv;           // row 0, feature t
        s->At[t*68] = bv;       // ppos[0] = 0
    }
    for (int d = jq; d < 6; d += 4) {
        float acc = 0.f;
        #pragma unroll
        for (int m=0;m<16;++m)
            acc = fmaf(s->pts[m*6+d], g_lin1T[m*64+f], acc);
        s->A[(1+d)*64 + f] = acc;
        s->At[f*68 + 16 + d] = acc;   // ppos[1+d] = 16+d
    }
    __syncthreads();

    float acc[16];
    for (int l = 0; l < 4; ++l) {
        {   // stage gp_w: W[f*65+w] via float4 loads
            const float4* gw4 = reinterpret_cast<const float4*>(gp_w + l*4096);
            #pragma unroll
            for (int r=0;r<4;++r) {
                const int e4 = r*256+t;
                const float4 v = gw4[e4];
                const int e = e4*4, ff = e>>6, w = e&63;
                s->W[ff*65+w+0] = v.x;
                s->W[ff*65+w+1] = v.y;
                s->W[ff*65+w+2] = v.z;
                s->W[ff*65+w+3] = v.w;
            }
        }
        switch (jq) {
            case 0:  sec_lin<0>(s->A, s->Bvt, l, f); break;
            case 1:  sec_lin<1>(s->A, s->Bvt, l, f); break;
            case 2:  sec_lin<2>(s->A, s->Bvt, l, f); break;
            default: sec_lin<3>(s->A, s->Bvt, l, f); break;
        }
        __syncthreads();
        switch (jq) {
            case 0:  sec_fact<0>(s->Bvt+f*68, s->F+f, gp_a, l, f); break;
            case 1:  sec_fact<1>(s->Bvt+f*68, s->F+f, gp_a, l, f); break;
            case 2:  sec_fact<2>(s->Bvt+f*68, s->F+f, gp_a, l, f); break;
            default: sec_fact<3>(s->Bvt+f*68, s->F+f, gp_a, l, f); break;
        }
        __syncthreads();
        switch (jq) {
            case 0:  sec_gp<0>(s->At+f*68, s->Bvt+f*68, s->W+f*65, s->F+f, acc); break;
            case 1:  sec_gp<1>(s->At+f*68, s->Bvt+f*68, s->W+f*65, s->F+f, acc); break;
            case 2:  sec_gp<2>(s->At+f*68, s->Bvt+f*68, s->W+f*65, s->F+f, acc); break;
            default: sec_gp<3>(s->At+f*68, s->Bvt+f*68, s->W+f*65, s->F+f, acc); break;
        }
        __syncthreads();
        switch (jq) {
            case 0:  sec_store<0>(s->A, s->At, f, l, acc); break;
            case 1:  sec_store<1>(s->A, s->At, f, l, acc); break;
            case 2:  sec_store<2>(s->A, s->At, f, l, acc); break;
            default: sec_store<3>(s->A, s->At, f, l, acc); break;
        }
        __syncthreads();
    }

    // epilogue: norms, MLP, loss
    {
        const float4* Xp = reinterpret_cast<const float4*>(s->At + f*68 + jq*16);
        float sum = 0.f;
        #pragma unroll
        for (int r=0;r<4;++r) {
            const float4 v = Xp[r];
            sum = fmaf(v.x, v.x, sum);
            sum = fmaf(v.y, v.y, sum);
            sum = fmaf(v.z, v.z, sum);
            sum = fmaf(v.w, v.w, sum);
        }
        s->F[jq*64+f] = sum;
    }
    {   // stage mlp_w1 -> Bvt[f*65+n] via float4 (reuse Bvt storage)
        const float4* mw4 = reinterpret_cast<const float4*>(mlp_w1);
        #pragma unroll
        for (int r=0;r<4;++r) {
            const int e4 = r*256+t;
            const float4 v = mw4[e4];
            const int e = e4*4, n = e>>6, ff = e&63;
            s->Bvt[(ff+0)*65+n] = v.x;
            s->Bvt[(ff+1)*65+n] = v.y;
            s->Bvt[(ff+2)*65+n] = v.z;
            s->Bvt[(ff+3)*65+n] = v.w;
        }
    }
    __syncthreads();
    if (t < 64) s->y[t] = sqrtf(s->F[t] + s->F[64+t] + s->F[128+t] + s->F[192+t]);
    __syncthreads();
    if (t < 64) {
        float a = mlp_b1[t];
        #pragma unroll
        for (int ff=0;ff<64;++ff)
            a = fmaf(s->y[ff], s->Bvt[ff*65+t], a);
        const float sig = 1.f/(1.f+expf(-a));
        s->h[t] = a * sig * mlp_w2[t];
    }
    __syncthreads();
    if (t == 0) {
        float p = mlp_b2[0];
        for (int n=0;n<64;++n) p += s->h[n];
        const float d = p - products[b];
        lossp[b] = d*d;
    }

    // fused mean-reduce: last CTA to finish does a deterministic tree sum
    if (do_mean) {
        __threadfence();
        __shared__ unsigned rank_s;
        if (t == 0) rank_s = atomicAdd(&g_done, 1u);
        __syncthreads();
        if (rank_s == NB - 1) {
            s->F[t] = lossp[t];
            __syncthreads();
            for (int sft = NB/2; sft > 0; sft >>= 1) {
                if (t < sft) s->F[t] += s->F[t+sft];
                __syncthreads();
            }
            if (t == 0) meanp[0] = s->F[0] * (1.0f/(float)NB);
        }
    }
}

extern "C" void kernel_launch(void* const* d_in, const int* in_sizes, int n_in,
                              void* d_out, int out_size)
{
    const float* points   = (const float*)d_in[0];
    const float* products = (const float*)d_in[1];
    const float* lin_w    = (const float*)d_in[2];
    const float* lin_b    = (const float*)d_in[3];
    const float* gp_lin_w = (const float*)d_in[4];
    const float* gp_a     = (const float*)d_in[5];
    const float* gp_w     = (const float*)d_in[6];
    const float* mlp_w1   = (const float*)d_in[7];
    const float* mlp_b1   = (const float*)d_in[8];
    const float* mlp_w2   = (const float*)d_in[9];
    const float* mlp_b2   = (const float*)d_in[10];
    float* out = (float*)d_out;

    static bool attr_set = false;
    if (!attr_set) {
        cudaFuncSetAttribute(ch_main, cudaFuncAttributeMaxDynamicSharedMemorySize,
                             (int)sizeof(SM));
        attr_set = true;
    }

    ch_init<<<65, 256>>>(gp_lin_w, lin_w);

    float* lossp;
    int do_mean = 1;
    if (out_size >= NB + 1) {
        lossp = out + 1;
    } else if (out_size == NB) {
        lossp = out; do_mean = 0;
    } else {
        void* p = nullptr;
        cudaGetSymbolAddress(&p, g_loss_scratch);
        lossp = (float*)p;
    }

    ch_main<<<NB, 256, sizeof(SM)>>>(points, products, lin_b, gp_a, gp_w,
                                     mlp_w1, mlp_b1, mlp_w2, mlp_b2,
                                     lossp, out, do_mean);
}

// round 15
// speedup vs baseline: 1.7612x; 1.4877x over previous
#include <cuda_runtime.h>

constexpr int NB = 256;

__host__ __device__ constexpr int cpopc(int x){int c=0;while(x){c+=x&1;x>>=1;}return c;}
__host__ __device__ constexpr int MAXG(int l){ return l==0?1 : l==1?2 : l==2?4 : 6; }

struct Alg {
    int qt[64];
    int gr[64];           // grade of row
    short kk[64][64];     // k(i,j)
    short sg[64][64];     // sign bit (1 = negative)
    int   cls[4][20];
    int   ncl[4];
    int   perm[4][16];    // row assignment per jq-group (class-grouped)
    int   permAll[64];    // storage order p -> row i
    int   ppos[64];       // row i -> storage position p
};
constexpr Alg build_alg(){
    Alg a{};
    int mask[64]={}, pos[64]={};
    int idx=0;
    for(int g=0;g<=6;++g) for(int m=0;m<64;++m) if(cpopc(m)==g){mask[idx]=m;idx++;}
    for(int i=0;i<64;++i) pos[mask[i]]=i;
    for(int i=0;i<64;++i){
        a.qt[i]=cpopc(mask[i])&3;
        a.gr[i]=cpopc(mask[i]);
        a.cls[a.qt[i]][a.ncl[a.qt[i]]]=i;
        a.ncl[a.qt[i]]++;
    }
    for(int i=0;i<64;++i) for(int j=0;j<64;++j){
        const int mk=mask[i]^mask[j];
        const int k=pos[mk];
        int s=0,t=mask[i]>>1;
        while(t){s+=cpopc(t&mk);t>>=1;}
        a.kk[i][j]=(short)k;
        a.sg[i][j]=(short)(s&1);
    }
    for(int q=0;q<16;++q) a.perm[0][q]=a.cls[0][q];
    for(int q=0;q<12;++q) a.perm[1][q]=a.cls[1][q];
    for(int q=0;q<4; ++q) a.perm[1][12+q]=a.cls[3][q];
    for(int q=0;q<16;++q) a.perm[2][q]=a.cls[2][q];
    for(int q=0;q<16;++q) a.perm[3][q]=a.cls[3][4+q];
    for(int g=0;g<4;++g) for(int q=0;q<16;++q){
        a.permAll[g*16+q]=a.perm[g][q];
        a.ppos[a.perm[g][q]]=g*16+q;
    }
    return a;
}
__device__ constexpr Alg ALG = build_alg();

typedef unsigned long long ull;

__device__ __forceinline__ ull fma2(ull a, ull b, ull c){
    ull r; asm("fma.rn.f32x2 %0, %1, %2, %3;" : "=l"(r) : "l"(a), "l"(b), "l"(c)); return r;
}
__device__ __forceinline__ void upk2(ull v, float& lo, float& hi){
    unsigned x, y;
    asm("mov.b64 {%0, %1}, %2;" : "=r"(x), "=r"(y) : "l"(v));
    lo = __uint_as_float(x); hi = __uint_as_float(y);
}

__device__ ull      g_lwT2[4*4*32*64];   // [l][c][mp][f] : (m=2mp, 2mp+1) pair
__device__ float    g_lin1T[1024];       // [m][f]
__device__ float    g_loss_scratch[NB];
__device__ unsigned g_done;

// Init: output-centric — scattered loads, coalesced ull stores.
__global__ void ch_init(const float* __restrict__ gp_lin_w,
                        const float* __restrict__ lin_w)
{
    const int t = threadIdx.x;
    if (blockIdx.x < 64) {
        const int o = blockIdx.x*256 + t;          // ((l*4+c)*32+mp)*64+f
        const int f = o & 63, mp = (o>>6)&31, c = (o>>11)&3, l = o>>13;
        const float a = gp_lin_w[((l*64+f)*64 + 2*mp  )*4 + c];
        const float b = gp_lin_w[((l*64+f)*64 + 2*mp+1)*4 + c];
        g_lwT2[o] = ((ull)__float_as_uint(b) << 32) | (ull)__float_as_uint(a);
    } else {
        if (t == 0) g_done = 0u;
        #pragma unroll
        for (int r=0;r<4;++r){
            const int e=r*256+t, m=e>>6, f=e&63;
            g_lin1T[e] = lin_w[(f*16+m)*4 + 1];
        }
    }
}

struct SM {
    float A[4096];      // x row-major [i*64+f]
    float At[4352];     // x transposed/permuted [f*68+p]
    float Bvt[4352];    // xr transposed/permuted [f*68+p]; reused for mlp_w1
    float W[4160];      // gp_w [f*65+widx]
    float F[256];       // factors [c*64+f] / epilogue partials / reduce
    float Fp[256];      // norm partials per group [g*64+f]
    float Fp2[64];      // group1's class-3 extra partial
    float y[64], h[64], pts[96];
};

template<int JQ, int G>
__device__ __forceinline__ void sec_lin(const float* __restrict__ Ash,
                                        float* __restrict__ Bvt,
                                        float* __restrict__ Fp,
                                        float* __restrict__ Fp2,
                                        int l, int f)
{
    ull LW2[32];
    float out[16];
    #pragma unroll
    for (int q=0;q<16;++q) {
        const int i = ALG.perm[JQ][q];
        if (ALG.gr[i] <= G) {
            if (q==0 || ALG.qt[ALG.perm[JQ][q]] != ALG.qt[ALG.perm[JQ][q-1]]) {
                const ull* p = g_lwT2 + ((l*4 + ALG.qt[i])*32)*64 + f;
                #pragma unroll
                for (int mp=0;mp<32;++mp) LW2[mp] = p[mp*64];
            }
            const ulonglong2* Ar = reinterpret_cast<const ulonglong2*>(Ash + i*64);
            ull acca = 0ull, accb = 0ull;
            #pragma unroll
            for (int u=0;u<16;++u){
                const ulonglong2 av = Ar[u];
                acca = fma2(LW2[2*u+0], av.x, acca);
                accb = fma2(LW2[2*u+1], av.y, accb);
            }
            float a0,a1,b0,b1;
            upk2(acca, a0, a1);
            upk2(accb, b0, b1);
            out[q] = (a0+b0) + (a1+b1);
        } else {
            out[q] = 0.f;
        }
    }
    float4* dst = reinterpret_cast<float4*>(Bvt + f*68 + JQ*16);
    #pragma unroll
    for (int r=0;r<4;++r)
        dst[r] = make_float4(out[4*r+0], out[4*r+1], out[4*r+2], out[4*r+3]);

    // norm partials from registers: primary class = JQ; group1 extra = class 3
    float pa = 0.f, pb = 0.f;
    #pragma unroll
    for (int q=0;q<16;++q) {
        if (ALG.qt[ALG.perm[JQ][q]] == JQ) pa = fmaf(out[q], out[q], pa);
        else                               pb = fmaf(out[q], out[q], pb);
    }
    Fp[JQ*64+f] = pa;
    if (JQ == 1) Fp2[f] = pb;
}

template<int C>
__device__ __forceinline__ void sec_fact(const float* __restrict__ Fp,
                                         const float* __restrict__ Fp2,
                                         float* __restrict__ Ff,
                                         const float* __restrict__ gp_a,
                                         int l, int f)
{
    float s = Fp[C*64+f];
    if (C == 3) s += Fp2[f];
    const float nrm = sqrtf(fmaxf(s, 1e-12f));
    const float av  = gp_a[(l*64+f)*4 + C];
    const float sig = 1.f/(1.f+expf(-av));
    Ff[C*64] = 1.f/(fmaf(sig, nrm-1.f, 1.f) + 1e-6f);
}

template<int JQ, int G>
__device__ __forceinline__ void sec_gp(const float* __restrict__ Atf,
                                       const float* __restrict__ Bvtf,
                                       const float* __restrict__ Wf,
                                       const float* __restrict__ Ff,
                                       float (&acc)[16])
{
    constexpr int CJ0 = (JQ==0) ? 0 : (JQ==1 ? 1 : (JQ==2 ? 2 : 3));
    constexpr int NCJ = (JQ==1) ? 2 : 1;

    float fc[4];
    #pragma unroll
    for (int c=0;c<4;++c) fc[c] = Ff[c*64];

    float B[64];
    {
        const float4* Bp = reinterpret_cast<const float4*>(Bvtf);
        #pragma unroll
        for (int p4=0;p4<16;++p4){
            const bool any = (ALG.gr[ALG.permAll[p4*4+0]] <= G) ||
                             (ALG.gr[ALG.permAll[p4*4+1]] <= G) ||
                             (ALG.gr[ALG.permAll[p4*4+2]] <= G) ||
                             (ALG.gr[ALG.permAll[p4*4+3]] <= G);
            if (any) {
                const float4 v = Bp[p4];
                #pragma unroll
                for (int h=0;h<4;++h){
                    const int k = ALG.permAll[p4*4+h];
                    if (ALG.gr[k] <= G) {
                        const float bv = (h==0)?v.x:(h==1)?v.y:(h==2)?v.z:v.w;
                        B[k] = bv * fc[ALG.qt[k]];
                    }
                }
            }
        }
    }

    float Wreg[NCJ*16];
    #pragma unroll
    for (int ci=0;ci<4;++ci)
        #pragma unroll
        for (int ck=0;ck<4;++ck) {
            Wreg[ci*4+ck] = Wf[(ci*4+CJ0)*4+ck];
            if (NCJ==2) Wreg[16+ci*4+ck] = Wf[(ci*4+3)*4+ck];
        }

    #pragma unroll
    for (int q=0;q<16;++q) acc[q]=0.f;

    const float4* Xp = reinterpret_cast<const float4*>(Atf);
    #pragma unroll
    for (int p4=0;p4<16;++p4) {
        const bool any = (ALG.gr[ALG.permAll[p4*4+0]] <= G) ||
                         (ALG.gr[ALG.permAll[p4*4+1]] <= G) ||
                         (ALG.gr[ALG.permAll[p4*4+2]] <= G) ||
                         (ALG.gr[ALG.permAll[p4*4+3]] <= G);
        if (!any) continue;
        const float4 xv = Xp[p4];
        #pragma unroll
        for (int h=0;h<4;++h) {
            const int i = ALG.permAll[p4*4+h];
            if (ALG.gr[i] > G) continue;
            const float xi = (h==0)?xv.x:(h==1)?xv.y:(h==2)?xv.z:xv.w;
            const int qti = ALG.qt[i];
            float XW[NCJ*4];
            #pragma unroll
            for (int ck=0;ck<4;++ck) {
                XW[ck] = xi * Wreg[qti*4+ck];
                if (NCJ==2) XW[4+ck] = xi * Wreg[16+qti*4+ck];
            }
            #pragma unroll
            for (int q=0;q<16;++q) {
                const int j  = ALG.perm[JQ][q];
                const int k  = ALG.kk[i][j];
                if (ALG.gr[k] > G) continue;       // operand xr support gate
                const int ck = ALG.qt[k];
                const int slot = (JQ==1 && q>=12) ? 1 : 0;
                const float xw = XW[slot*4+ck];
                if (ALG.sg[i][j]) acc[q] = fmaf(xw, -B[k], acc[q]);
                else              acc[q] = fmaf(xw,  B[k], acc[q]);
            }
        }
    }
}

template<int JQ, int GN>   // GN = next layer's support bound; -1 = last layer
__device__ __forceinline__ void sec_store(float* __restrict__ Ash,
                                          float* __restrict__ At,
                                          int f, const float (&acc)[16])
{
    float4* dstT = reinterpret_cast<float4*>(At + f*68 + JQ*16);
    #pragma unroll
    for (int r=0;r<4;++r)
        dstT[r] = make_float4(acc[4*r+0], acc[4*r+1], acc[4*r+2], acc[4*r+3]);
    if (GN >= 0) {
        #pragma unroll
        for (int q=0;q<16;++q) {
            const int i = ALG.perm[JQ][q];
            if (ALG.gr[i] <= GN)
                Ash[i*64 + f] = acc[q];
        }
    }
}

template<int L>
__device__ __forceinline__ void layer(SM* s,
                                      const float* __restrict__ gp_a,
                                      const float* __restrict__ gp_w,
                                      int t, int f, int jq)
{
    constexpr int G  = MAXG(L);
    constexpr int GN = (L<3) ? MAXG(L+1) : -1;

    {   // stage gp_w: W[f*65+w] via float4 loads
        const float4* gw4 = reinterpret_cast<const float4*>(gp_w + L*4096);
        #pragma unroll
        for (int r=0;r<4;++r) {
            const int e4 = r*256+t;
            const float4 v = gw4[e4];
            const int e = e4*4, ff = e>>6, w = e&63;
            s->W[ff*65+w+0] = v.x;
            s->W[ff*65+w+1] = v.y;
            s->W[ff*65+w+2] = v.z;
            s->W[ff*65+w+3] = v.w;
        }
    }
    switch (jq) {
        case 0:  sec_lin<0,G>(s->A, s->Bvt, s->Fp, s->Fp2, L, f); break;
        case 1:  sec_lin<1,G>(s->A, s->Bvt, s->Fp, s->Fp2, L, f); break;
        case 2:  sec_lin<2,G>(s->A, s->Bvt, s->Fp, s->Fp2, L, f); break;
        default: sec_lin<3,G>(s->A, s->Bvt, s->Fp, s->Fp2, L, f); break;
    }
    __syncthreads();
    switch (jq) {
        case 0:  sec_fact<0>(s->Fp, s->Fp2, s->F+f, gp_a, L, f); break;
        case 1:  sec_fact<1>(s->Fp, s->Fp2, s->F+f, gp_a, L, f); break;
        case 2:  sec_fact<2>(s->Fp, s->Fp2, s->F+f, gp_a, L, f); break;
        default: sec_fact<3>(s->Fp, s->Fp2, s->F+f, gp_a, L, f); break;
    }
    __syncthreads();
    float acc[16];
    switch (jq) {
        case 0:  sec_gp<0,G>(s->At+f*68, s->Bvt+f*68, s->W+f*65, s->F+f, acc); break;
        case 1:  sec_gp<1,G>(s->At+f*68, s->Bvt+f*68, s->W+f*65, s->F+f, acc); break;
        case 2:  sec_gp<2,G>(s->At+f*68, s->Bvt+f*68, s->W+f*65, s->F+f, acc); break;
        default: sec_gp<3,G>(s->At+f*68, s->Bvt+f*68, s->W+f*65, s->F+f, acc); break;
    }
    __syncthreads();
    switch (jq) {
        case 0:  sec_store<0,GN>(s->A, s->At, f, acc); break;
        case 1:  sec_store<1,GN>(s->A, s->At, f, acc); break;
        case 2:  sec_store<2,GN>(s->A, s->At, f, acc); break;
        default: sec_store<3,GN>(s->A, s->At, f, acc); break;
    }
    __syncthreads();
}

__global__ void __launch_bounds__(256, 2)
ch_main(const float* __restrict__ points,
        const float* __restrict__ products,
        const float* __restrict__ lin_b,
        const float* __restrict__ gp_a,
        const float* __restrict__ gp_w,
        const float* __restrict__ mlp_w1,
        const float* __restrict__ mlp_b1,
        const float* __restrict__ mlp_w2,
        const float* __restrict__ mlp_b2,
        float* __restrict__ lossp,
        float* __restrict__ meanp,
        int do_mean)
{
    extern __shared__ unsigned char smraw[];
    SM* s = reinterpret_cast<SM*>(smraw);

    const int t  = threadIdx.x;
    const int b  = blockIdx.x;
    const int f  = t & 63;
    const int jq = t >> 6;

    if (t < 96) s->pts[t] = points[b*96 + t];
    for (int e = 448 + t; e < 4096; e += 256) s->A[e] = 0.f;
    for (int e = t; e < 4352; e += 256) s->At[e] = 0.f;
    __syncthreads();

    if (t < 64) {
        const float bv = lin_b[t];
        s->A[t] = bv;
        s->At[t*68] = bv;       // ppos[0] = 0
    }
    for (int d = jq; d < 6; d += 4) {
        float acc = 0.f;
        #pragma unroll
        for (int m=0;m<16;++m)
            acc = fmaf(s->pts[m*6+d], g_lin1T[m*64+f], acc);
        s->A[(1+d)*64 + f] = acc;
        s->At[f*68 + 16 + d] = acc;   // ppos[1+d] = 16+d
    }
    __syncthreads();

    layer<0>(s, gp_a, gp_w, t, f, jq);
    layer<1>(s, gp_a, gp_w, t, f, jq);
    layer<2>(s, gp_a, gp_w, t, f, jq);
    layer<3>(s, gp_a, gp_w, t, f, jq);

    // epilogue: norms, MLP, loss
    {
        const float4* Xp = reinterpret_cast<const float4*>(s->At + f*68 + jq*16);
        float sum = 0.f;
        #pragma unroll
        for (int r=0;r<4;++r) {
            const float4 v = Xp[r];
            sum = fmaf(v.x, v.x, sum);
            sum = fmaf(v.y, v.y, sum);
            sum = fmaf(v.z, v.z, sum);
            sum = fmaf(v.w, v.w, sum);
        }
        s->F[jq*64+f] = sum;
    }
    {   // stage mlp_w1 -> Bvt[f*65+n]
        const float4* mw4 = reinterpret_cast<const float4*>(mlp_w1);
        #pragma unroll
        for (int r=0;r<4;++r) {
            const int e4 = r*256+t;
            const float4 v = mw4[e4];
            const int e = e4*4, n = e>>6, ff = e&63;
            s->Bvt[(ff+0)*65+n] = v.x;
            s->Bvt[(ff+1)*65+n] = v.y;
            s->Bvt[(ff+2)*65+n] = v.z;
            s->Bvt[(ff+3)*65+n] = v.w;
        }
    }
    __syncthreads();
    if (t < 64) s->y[t] = sqrtf(s->F[t] + s->F[64+t] + s->F[128+t] + s->F[192+t]);
    __syncthreads();
    if (t < 64) {
        float a = mlp_b1[t];
        #pragma unroll
        for (int ff=0;ff<64;++ff)
            a = fmaf(s->y[ff], s->Bvt[ff*65+t], a);
        const float sig = 1.f/(1.f+expf(-a));
        s->h[t] = a * sig * mlp_w2[t];
    }
    __syncthreads();
    if (t == 0) {
        float p = mlp_b2[0];
        for (int n=0;n<64;++n) p += s->h[n];
        const float d = p - products[b];
        lossp[b] = d*d;
    }

    if (do_mean) {
        __threadfence();
        __shared__ unsigned rank_s;
        if (t == 0) rank_s = atomicAdd(&g_done, 1u);
        __syncthreads();
        if (rank_s == NB - 1) {
            s->F[t] = lossp[t];
            __syncthreads();
            for (int sft = NB/2; sft > 0; sft >>= 1) {
                if (t < sft) s->F[t] += s->F[t+sft];
                __syncthreads();
            }
            if (t == 0) meanp[0] = s->F[0] * (1.0f/(float)NB);
        }
    }
}

extern "C" void kernel_launch(void* const* d_in, const int* in_sizes, int n_in,
                              void* d_out, int out_size)
{
    const float* points   = (const float*)d_in[0];
    const float* products = (const float*)d_in[1];
    const float* lin_w    = (const float*)d_in[2];
    const float* lin_b    = (const float*)d_in[3];
    const float* gp_lin_w = (const float*)d_in[4];
    const float* gp_a     = (const float*)d_in[5];
    const float* gp_w     = (const float*)d_in[6];
    const float* mlp_w1   = (const float*)d_in[7];
    const float* mlp_b1   = (const float*)d_in[8];
    const float* mlp_w2   = (const float*)d_in[9];
    const float* mlp_b2   = (const float*)d_in[10];
    float* out = (float*)d_out;

    static bool attr_set = false;
    if (!attr_set) {
        cudaFuncSetAttribute(ch_main, cudaFuncAttributeMaxDynamicSharedMemorySize,
                             (int)sizeof(SM));
        attr_set = true;
    }

    ch_init<<<65, 256>>>(gp_lin_w, lin_w);

    float* lossp;
    int do_mean = 1;
    if (out_size >= NB + 1) {
        lossp = out + 1;
    } else if (out_size == NB) {
        lossp = out; do_mean = 0;
    } else {
        void* p = nullptr;
        cudaGetSymbolAddress(&p, g_loss_scratch);
        lossp = (float*)p;
    }

    ch_main<<<NB, 256, sizeof(SM)>>>(points, products, lin_b, gp_a, gp_w,
                                     mlp_w1, mlp_b1, mlp_w2, mlp_b2,
                                     lossp, out, do_mean);
}